// round 6
// baseline (speedup 1.0000x reference)
#include <cuda_runtime.h>
#include <cuda_bf16.h>

// ============================================================================
// TFCRNN teacher-forcing GRU. B=32, T=512, IN=256, H=2048, C=16.
// Persistent kernel, 128 CTAs x 256 thr, 1 grid barrier/step.
//
// R6 == R4 design, but the W tile pipeline uses register-staged prefetch
// (LDG next tile into regs during current tile's compute, then STS) instead
// of cp.async — removes the only unproven machinery from the R4/R5 attempts
// that failed at container level.
//
// W streamed ONCE per step through smem 64-k tiles, consumed as 32B
// two-address LDS broadcasts. Lane = (kk = k-half, bh = batch mod 16); each
// lane accumulates 2 batches (bh, bh+16) for the warp's 2 hidden units x 4
// gate-parts. One shfl_xor(16) folds k-halves. h and x quad-packed [k4][b]
// float4 for coalesced LDG.128.
//
// Identities: scheduled prob == 0.9 for all t -> flag = rand < 900;
//             sigmoid(v) > 0.5 <=> v > 0.
// ============================================================================

typedef unsigned long long ull;

#define BATCH 32
#define TSTEPS 512
#define INF 256
#define HID 2048
#define CLS 16
#define NCTA 128
#define NTHR 256
#define NTILE 36   // 4 x-tiles (256k) + 32 h-tiles (2048k), 64 k each
#define TILE_Q 768 // 48 rows x 16 float4 per tile

__device__ float4 g_hq[2][512 * 32];       // h quad-packed [k4][b], ping-pong
__device__ float4 g_xq[TSTEPS * 64 * 32];  // x transposed [t][k4][b]
__device__ float g_tf[CLS * BATCH];
__device__ unsigned g_bar_count, g_bar_gen, g_tf_flag;

// ---------------- helpers ----------------------------------------------------
__device__ __forceinline__ ull ffma2(ull a, ull b, ull c) {
    ull d;
    asm("fma.rn.f32x2 %0, %1, %2, %3;" : "=l"(d) : "l"(a), "l"(b), "l"(c));
    return d;
}
__device__ __forceinline__ float2 unpack2(ull v) {
    float2 f;
    asm("mov.b64 {%0, %1}, %2;" : "=f"(f.x), "=f"(f.y) : "l"(v));
    return f;
}
__device__ __forceinline__ float sigmoidf_(float v) {
    return 1.0f / (1.0f + expf(-v));
}

// ---------------- grid barrier ----------------------------------------------
__device__ __forceinline__ void grid_barrier(unsigned& gen) {
    __syncthreads();
    if (threadIdx.x == 0) {
        __threadfence();
        unsigned arr = atomicAdd(&g_bar_count, 1u);
        if (arr == NCTA - 1) {
            g_bar_count = 0;
            __threadfence();
            atomicExch(&g_bar_gen, gen + 1);
        } else {
            unsigned g;
            do {
                asm volatile("ld.acquire.gpu.u32 %0, [%1];"
                             : "=r"(g) : "l"(&g_bar_gen) : "memory");
                if (g == gen) __nanosleep(32);
            } while (g == gen);
        }
        __threadfence();
    }
    gen++;
    __syncthreads();
}

// ---------------- reset ------------------------------------------------------
__global__ void reset_kernel() {
    int i = blockIdx.x * blockDim.x + threadIdx.x;
    if (i < 512 * 32) g_hq[0][i] = make_float4(0.f, 0.f, 0.f, 0.f);
    if (i < CLS * BATCH) g_tf[i] = 0.0f;
    if (i == 0) { g_bar_count = 0; g_bar_gen = 0; g_tf_flag = 0; }
}

// ---------------- per-tile MAC ----------------------------------------------
// op: quad-packed operand base for this tile (16 k4 x 32 b float4)
// sw: smem W tile (48 rows x 16 float4, k-halves interleaved: s = j2*2+kk)
__device__ __forceinline__ void tile_mac(const float4* __restrict__ op,
                                         const float4* __restrict__ sw,
                                         int wid, int kk, int bh,
                                         ull (&aR)[2][2], ull (&aZ)[2][2],
                                         ull (&aNI)[2][2]) {
#pragma unroll
    for (int j2 = 0; j2 < 8; j2++) {
        ulonglong2 hA = *(const ulonglong2*)&op[(kk * 8 + j2) * 32 + bh];
        ulonglong2 hB = *(const ulonglong2*)&op[(kk * 8 + j2) * 32 + bh + 16];
        const int sidx = j2 * 2 + kk;
#pragma unroll
        for (int u = 0; u < 2; u++) {
            const int rb = 2 * wid + u;
            ulonglong2 w;
            w = *(const ulonglong2*)&sw[(0 * 16 + rb) * 16 + sidx];
            aR[u][0] = ffma2(hA.x, w.x, aR[u][0]);
            aR[u][0] = ffma2(hA.y, w.y, aR[u][0]);
            aR[u][1] = ffma2(hB.x, w.x, aR[u][1]);
            aR[u][1] = ffma2(hB.y, w.y, aR[u][1]);
            w = *(const ulonglong2*)&sw[(1 * 16 + rb) * 16 + sidx];
            aZ[u][0] = ffma2(hA.x, w.x, aZ[u][0]);
            aZ[u][0] = ffma2(hA.y, w.y, aZ[u][0]);
            aZ[u][1] = ffma2(hB.x, w.x, aZ[u][1]);
            aZ[u][1] = ffma2(hB.y, w.y, aZ[u][1]);
            w = *(const ulonglong2*)&sw[(2 * 16 + rb) * 16 + sidx];
            aNI[u][0] = ffma2(hA.x, w.x, aNI[u][0]);
            aNI[u][0] = ffma2(hA.y, w.y, aNI[u][0]);
            aNI[u][1] = ffma2(hB.x, w.x, aNI[u][1]);
            aNI[u][1] = ffma2(hB.y, w.y, aNI[u][1]);
        }
    }
}

// ---------------- persistent kernel -----------------------------------------
__global__ __launch_bounds__(NTHR, 1) void tfcrnn_persistent(
    const float* __restrict__ x, const float* __restrict__ y,
    const int* __restrict__ rand_vals, const float* __restrict__ W_ih,
    const float* __restrict__ W_hh, const float* __restrict__ b_ih,
    const float* __restrict__ b_hh, const float* __restrict__ W_cls,
    const float* __restrict__ b_cls, float* __restrict__ out) {
    const int tid = threadIdx.x;
    const int lane = tid & 31;
    const int wid = tid >> 5;
    const int cta = blockIdx.x;
    const int kk = lane >> 4;  // k-half
    const int bh = lane & 15;  // batch (this lane also does bh+16)
    unsigned gen = 0;

    __shared__ float4 s_w[2][TILE_Q];
    __shared__ float s_cls[8][BATCH];

    // this thread's 3 W-fetch slots (fid = tid + j*256)
    int f_r[3], f_c[3];
#pragma unroll
    for (int j = 0; j < 3; j++) {
        int fid = tid + j * 256;
        f_r[j] = fid >> 4;
        f_c[j] = fid & 15;
    }

    // ---- one-time: transpose x into quad-packed g_xq ----
    for (int o = cta * NTHR + tid; o < TSTEPS * 64 * 32; o += NCTA * NTHR) {
        int b = o & 31, k4 = (o >> 5) & 63, tt = o >> 11;
        g_xq[o] = *(const float4*)&x[((size_t)b * TSTEPS + tt) * INF + k4 * 4];
    }
    grid_barrier(gen);

    const int u = cta * 16 + 2 * wid + kk;  // this lane's update unit
    const int cta16 = cta * 16;
    const float bRc = b_ih[u] + b_hh[u];
    const float bZc = b_ih[HID + u] + b_hh[HID + u];
    const float bIc = b_ih[2 * HID + u];
    const float bNc = b_hh[2 * HID + u];

    for (int t = 0; t < TSTEPS; t++) {
        const float4* __restrict__ hq_in = g_hq[t & 1];
        float4* __restrict__ hq_out = g_hq[(t + 1) & 1];

        ull aR[2][2], aZ[2][2], aI[2][2], aN[2][2];
#pragma unroll
        for (int uu = 0; uu < 2; uu++)
#pragma unroll
            for (int hh = 0; hh < 2; hh++) {
                aR[uu][hh] = 0ull; aZ[uu][hh] = 0ull;
                aI[uu][hh] = 0ull; aN[uu][hh] = 0ull;
            }

        // ---- prologue: LDG tile 0 into regs ----
        float4 nt[3];
#pragma unroll
        for (int j = 0; j < 3; j++) {
            int gate = f_r[j] >> 4, uu = f_r[j] & 15;
            nt[j] = *(const float4*)(W_ih +
                                     (size_t)(gate * HID + cta16 + uu) * 272 +
                                     f_c[j] * 4);
        }

        // ---- tile loop: 4 x-tiles + 32 h-tiles ----
        for (int i = 0; i < NTILE; i++) {
            __syncthreads();  // prior consumers of buf[i&1] are done
#pragma unroll
            for (int j = 0; j < 3; j++)
                s_w[i & 1][f_r[j] * 16 + ((f_c[j] & 7) * 2 + (f_c[j] >> 3))] =
                    nt[j];
            __syncthreads();  // buf[i&1] holds tile i
            if (i + 1 < NTILE) {
                const int ni = i + 1;
#pragma unroll
                for (int j = 0; j < 3; j++) {
                    int gate = f_r[j] >> 4, uu = f_r[j] & 15;
                    const float* src =
                        (ni < 4)
                            ? W_ih + (size_t)(gate * HID + cta16 + uu) * 272 +
                                  ni * 64 + f_c[j] * 4
                            : W_hh + (size_t)(gate * HID + cta16 + uu) * 2048 +
                                  (ni - 4) * 64 + f_c[j] * 4;
                    nt[j] = *(const float4*)src;  // hidden under tile_mac
                }
            }
            const float4* sw = s_w[i & 1];
            if (i < 4)
                tile_mac(g_xq + ((size_t)t * 64 + i * 16) * 32, sw, wid, kk,
                         bh, aR, aZ, aI);
            else
                tile_mac(hq_in + (size_t)(i - 4) * 16 * 32, sw, wid, kk, bh,
                         aR, aZ, aN);
        }

        // ---- fold f32x2 + combine k-halves via shfl ----
        float fR[2][2], fZ[2][2], fI[2][2], fN[2][2];
#pragma unroll
        for (int uu = 0; uu < 2; uu++)
#pragma unroll
            for (int hh = 0; hh < 2; hh++) {
                float2 f;
                float v;
                f = unpack2(aR[uu][hh]); v = f.x + f.y;
                fR[uu][hh] = v + __shfl_xor_sync(0xffffffffu, v, 16);
                f = unpack2(aZ[uu][hh]); v = f.x + f.y;
                fZ[uu][hh] = v + __shfl_xor_sync(0xffffffffu, v, 16);
                f = unpack2(aI[uu][hh]); v = f.x + f.y;
                fI[uu][hh] = v + __shfl_xor_sync(0xffffffffu, v, 16);
                f = unpack2(aN[uu][hh]); v = f.x + f.y;
                fN[uu][hh] = v + __shfl_xor_sync(0xffffffffu, v, 16);
            }

        // ---- wait for tf(t-1) (hidden under GEMV above) ----
        if (tid == 0) {
            unsigned thr = 16u * (unsigned)t, v;
            do {
                asm volatile("ld.acquire.gpu.u32 %0, [%1];"
                             : "=r"(v) : "l"(&g_tf_flag) : "memory");
                if (v < thr) __nanosleep(32);
            } while (v < thr);
            __threadfence();
        }
        __syncthreads();

        // ---- tf segment: cols 256..271 of W_ih for unit u ----
        float tR0 = 0, tR1 = 0, tZ0 = 0, tZ1 = 0, tI0 = 0, tI1 = 0;
#pragma unroll
        for (int j4 = 0; j4 < 4; j4++) {
            float4 wR = *(const float4*)&W_ih[(size_t)u * 272 + 256 + j4 * 4];
            float4 wZ =
                *(const float4*)&W_ih[(size_t)(HID + u) * 272 + 256 + j4 * 4];
            float4 wI = *(const float4*)&W_ih[(size_t)(2 * HID + u) * 272 +
                                              256 + j4 * 4];
#pragma unroll
            for (int jj = 0; jj < 4; jj++) {
                int j = j4 * 4 + jj;
                float t0 = g_tf[j * 32 + bh];
                float t1 = g_tf[j * 32 + bh + 16];
                float wr = ((const float*)&wR)[jj];
                float wz = ((const float*)&wZ)[jj];
                float wi = ((const float*)&wI)[jj];
                tR0 = fmaf(t0, wr, tR0); tR1 = fmaf(t1, wr, tR1);
                tZ0 = fmaf(t0, wz, tZ0); tZ1 = fmaf(t1, wz, tZ1);
                tI0 = fmaf(t0, wi, tI0); tI1 = fmaf(t1, wi, tI1);
            }
        }

        // ---- gates + state update (this lane: unit u, b = bh, bh+16) ----
        {
            const int k4 = u >> 2, e = u & 3;
#pragma unroll
            for (int hh = 0; hh < 2; hh++) {
                const int b = bh + 16 * hh;
                float sR = (kk ? fR[1][hh] : fR[0][hh]) + (hh ? tR1 : tR0) +
                           bRc;
                float sZ = (kk ? fZ[1][hh] : fZ[0][hh]) + (hh ? tZ1 : tZ0) +
                           bZc;
                float sI = (kk ? fI[1][hh] : fI[0][hh]) + (hh ? tI1 : tI0) +
                           bIc;
                float sN = (kk ? fN[1][hh] : fN[0][hh]) + bNc;
                float hp = ((const float*)hq_in)[(size_t)(k4 * 32 + b) * 4 + e];
                float r = sigmoidf_(sR);
                float z = sigmoidf_(sZ);
                float n = tanhf(sI + r * sN);
                float hn = (1.0f - z) * n + z * hp;
                ((float*)hq_out)[(size_t)(k4 * 32 + b) * 4 + e] = hn;
            }
        }

        grid_barrier(gen);  // h(t) complete & visible

        // ---- classifier + teacher forcing: CTA c < 16 owns class c ----
        if (cta < CLS) {
            const int c = cta;
            const int b = lane;
            float acc = 0.0f;
            const int k4b = wid * 64;
#pragma unroll 8
            for (int k4 = k4b; k4 < k4b + 64; k4++) {
                float4 hv = hq_out[k4 * 32 + b];
                float4 wv = *(const float4*)&W_cls[(size_t)c * HID + k4 * 4];
                acc = fmaf(hv.x, wv.x, acc);
                acc = fmaf(hv.y, wv.y, acc);
                acc = fmaf(hv.z, wv.z, acc);
                acc = fmaf(hv.w, wv.w, acc);
            }
            s_cls[wid][b] = acc;
            __syncthreads();
            if (wid == 0) {
                float tot = b_cls[c];
#pragma unroll
                for (int w = 0; w < 8; w++) tot += s_cls[w][b];
                out[((size_t)b * TSTEPS + t) * CLS + c] = tot;
                float pred = (tot > 0.0f) ? 1.0f : 0.0f;
                bool fl = rand_vals[t * BATCH + b] < 900;
                g_tf[c * 32 + b] =
                    fl ? y[((size_t)b * TSTEPS + t) * CLS + c] : pred;
            }
            __syncthreads();
            if (tid == 0) {
                __threadfence();
                atomicAdd(&g_tf_flag, 1u);
            }
        }
    }
}

// ---------------- launch ----------------------------------------------------
extern "C" void kernel_launch(void* const* d_in, const int* in_sizes, int n_in,
                              void* d_out, int out_size) {
    const float* x     = (const float*)d_in[0];
    const float* y     = (const float*)d_in[1];
    const int*   rv    = (const int*)d_in[2];
    const float* W_ih  = (const float*)d_in[3];
    const float* W_hh  = (const float*)d_in[4];
    const float* b_ih  = (const float*)d_in[5];
    const float* b_hh  = (const float*)d_in[6];
    const float* W_cls = (const float*)d_in[7];
    const float* b_cls = (const float*)d_in[8];
    float* out = (float*)d_out;

    reset_kernel<<<64, 256>>>();
    tfcrnn_persistent<<<NCTA, NTHR>>>(x, y, rv, W_ih, W_hh, b_ih, b_hh, W_cls,
                                      b_cls, out);
}